// round 12
// baseline (speedup 1.0000x reference)
#include <cuda_runtime.h>
#include <cuda_fp16.h>
#include <math.h>
#include <stdint.h>

#define Bn  2
#define Sn  2048
#define Dn  2048
#define Hn  16
#define DKn 128
#define DVn 128
#define Ln  64

// ---------------- scratch (device globals) ----------------
__device__ __half g_wqkT[Hn * Ln * Dn];       // [1024][2048] absorbed Wq^T
__device__ float  g_bqk [Hn * Ln];
__device__ __half g_wvoT[Dn * Hn * Ln];       // [2048][1024] absorbed Wout^T
__device__ __half g_wlkT[Hn * Ln * Dn];       // [1024][2048] Wlk^T
__device__ __half g_wlvT[Hn * Ln * Dn];       // [1024][2048] Wlv^T
__device__ __half g_qh [Bn * Sn * Dn];        // fp16 copies of activations
__device__ __half g_kh [Bn * Sn * Dn];
__device__ __half g_vh [Bn * Sn * Dn];
__device__ __half g_q  [Bn * Hn * Sn * Ln];   // [B,H,S,L], pre-scaled log2e/sqrt(128)
__device__ __half g_lk [Bn * Hn * Sn * Ln];   // [B,H,S,L]
__device__ __half g_lvT[Bn * Hn * Ln * Sn];   // [B,H,L,S]
__device__ __half g_olat[Bn * Sn * Hn * Ln];  // [4096][1024]

// ---------------- helpers ----------------
__device__ __forceinline__ void ldsm4(uint32_t* r, uint32_t a) {
    asm volatile("ldmatrix.sync.aligned.m8n8.x4.shared.b16 {%0,%1,%2,%3}, [%4];"
                 : "=r"(r[0]), "=r"(r[1]), "=r"(r[2]), "=r"(r[3]) : "r"(a));
}
__device__ __forceinline__ void mma_f16(float* c, const uint32_t* a,
                                        uint32_t b0, uint32_t b1) {
    asm volatile(
        "mma.sync.aligned.m16n8k16.row.col.f32.f16.f16.f32 "
        "{%0,%1,%2,%3}, {%4,%5,%6,%7}, {%8,%9}, {%0,%1,%2,%3};\n"
        : "+f"(c[0]), "+f"(c[1]), "+f"(c[2]), "+f"(c[3])
        : "r"(a[0]), "r"(a[1]), "r"(a[2]), "r"(a[3]), "r"(b0), "r"(b1));
}
#define CPA16(dst, src) \
    asm volatile("cp.async.cg.shared.global [%0], [%1], 16;\n" :: "r"(dst), "l"(src))

// ---------------- fp32 -> fp16 conversion pass ----------------
struct RArgs { const float4* in[3]; uint4* out[3]; };
__global__ void __launch_bounds__(256) roundcp(RArgs ra, int n8)
{
    const float4* in = ra.in[blockIdx.y];
    uint4* out = ra.out[blockIdx.y];
    int i = blockIdx.x * 256 + threadIdx.x;
    if (i >= n8) return;
    float4 v0 = in[2 * i], v1 = in[2 * i + 1];
    __half2 h0 = __floats2half2_rn(v0.x, v0.y);
    __half2 h1 = __floats2half2_rn(v0.z, v0.w);
    __half2 h2 = __floats2half2_rn(v1.x, v1.y);
    __half2 h3 = __floats2half2_rn(v1.z, v1.w);
    uint4 o;
    o.x = *(uint32_t*)&h0; o.y = *(uint32_t*)&h1;
    o.z = *(uint32_t*)&h2; o.w = *(uint32_t*)&h3;
    out[i] = o;
}

// ---------------- weight transpose: [2048][1024] f32 -> [1024][2048] f16 ------------
__global__ void __launch_bounds__(256) wtrans(const float* __restrict__ in,
                                              __half* __restrict__ out)
{
    __shared__ float t[32][33];
    int x = threadIdx.x & 31, y = threadIdx.x >> 5;
    int bx = blockIdx.x, by = blockIdx.y;
#pragma unroll
    for (int i = 0; i < 32; i += 8)
        t[y + i][x] = in[(size_t)(bx * 32 + y + i) * 1024 + by * 32 + x];
    __syncthreads();
#pragma unroll
    for (int i = 0; i < 32; i += 8)
        out[(size_t)(by * 32 + y + i) * 2048 + bx * 32 + x] = __float2half_rn(t[x][y + i]);
}

// ---------------- absorbed weight: wqkT[hl][d] (coalesced, 512 threads) --------------
// block: (dtile, h); 512 threads. smem: wqs[128][133] f32, wkT[128][64] f32, os[64][128] f16
#define WQS_F (128 * 133)
#define WKT_F (128 * 64)
__global__ void __launch_bounds__(512) wqk3(const float* __restrict__ Wq,
                                            const float* __restrict__ Wkr,
                                            __half* __restrict__ out)
{
    extern __shared__ float sm[];
    float* wqs = sm;                       // [128][133]
    float* wkT = sm + WQS_F;               // [128][64]  wkT[dk][l]
    __half* os = (__half*)(sm + WQS_F + WKT_F);  // [64][128]

    const int tid = threadIdx.x;
    const int d0 = blockIdx.x * 128, h = blockIdx.y;

    for (int i = tid; i < Ln * DKn; i += 512) {
        int l = i >> 7, dk = i & 127;
        wkT[dk * 64 + l] = Wkr[i];
    }
#pragma unroll
    for (int p = 0; p < 8; p++) {
        int idx = tid + p * 512;
        int row = idx >> 5, c4 = (idx & 31) * 4;
        float4 v = *(const float4*)(Wq + (size_t)(d0 + row) * Dn + h * DKn + c4);
        float* w = &wqs[row * 133 + c4];
        w[0] = v.x; w[1] = v.y; w[2] = v.z; w[3] = v.w;
    }
    __syncthreads();

    const int dl = tid & 127, lq = tid >> 7;   // lq = 0..3 -> 16 l each
    float s[16];
#pragma unroll
    for (int j = 0; j < 16; j++) s[j] = 0.f;
    for (int dk = 0; dk < DKn; dk++) {
        float a = wqs[dl * 133 + dk];
        const float4* w4 = (const float4*)&wkT[dk * 64 + lq * 16];
#pragma unroll
        for (int jj = 0; jj < 4; jj++) {
            float4 w = w4[jj];
            s[4*jj+0] = fmaf(a, w.x, s[4*jj+0]);
            s[4*jj+1] = fmaf(a, w.y, s[4*jj+1]);
            s[4*jj+2] = fmaf(a, w.z, s[4*jj+2]);
            s[4*jj+3] = fmaf(a, w.w, s[4*jj+3]);
        }
    }
#pragma unroll
    for (int j = 0; j < 16; j++)
        os[(lq * 16 + j) * 128 + dl] = __float2half_rn(s[j]);
    __syncthreads();

    const uint4* os4 = (const uint4*)os;       // 64 l x 16 uint4
#pragma unroll
    for (int p = 0; p < 2; p++) {
        int idx = tid + p * 512;
        int l = idx >> 4, u = idx & 15;
        *(uint4*)&out[(size_t)(h * Ln + l) * Dn + d0 + u * 8] = os4[l * 16 + u];
    }
}

// ---------------- absorbed weight: wvoT[d][hl] (coalesced, 512 threads) --------------
__global__ void __launch_bounds__(512) wvo3(const float* __restrict__ Wvr,
                                            const float* __restrict__ Wout,
                                            __half* __restrict__ out)
{
    extern __shared__ float sm[];
    float* wos = sm;                       // [128][133]  wos[dv][d_local]
    float* wvT = sm + WQS_F;               // [128][64]   wvT[dv][l]
    __half* os = (__half*)(sm + WQS_F + WKT_F);  // [128][64]

    const int tid = threadIdx.x;
    const int d0 = blockIdx.x * 128, h = blockIdx.y;

    for (int i = tid; i < Ln * DVn; i += 512) {
        int l = i >> 7, dv = i & 127;
        wvT[dv * 64 + l] = Wvr[i];
    }
#pragma unroll
    for (int p = 0; p < 8; p++) {
        int idx = tid + p * 512;
        int dv = idx >> 5, c4 = (idx & 31) * 4;
        float4 v = *(const float4*)(Wout + (size_t)(h * DVn + dv) * Dn + d0 + c4);
        float* w = &wos[dv * 133 + c4];
        w[0] = v.x; w[1] = v.y; w[2] = v.z; w[3] = v.w;
    }
    __syncthreads();

    const int dl = tid & 127, lq = tid >> 7;
    float s[16];
#pragma unroll
    for (int j = 0; j < 16; j++) s[j] = 0.f;
    for (int dv = 0; dv < DVn; dv++) {
        float a = wos[dv * 133 + dl];
        const float4* w4 = (const float4*)&wvT[dv * 64 + lq * 16];
#pragma unroll
        for (int jj = 0; jj < 4; jj++) {
            float4 w = w4[jj];
            s[4*jj+0] = fmaf(a, w.x, s[4*jj+0]);
            s[4*jj+1] = fmaf(a, w.y, s[4*jj+1]);
            s[4*jj+2] = fmaf(a, w.z, s[4*jj+2]);
            s[4*jj+3] = fmaf(a, w.w, s[4*jj+3]);
        }
    }
#pragma unroll
    for (int j = 0; j < 16; j++)
        os[dl * 64 + lq * 16 + j] = __float2half_rn(s[j]);
    __syncthreads();

    const uint4* os4 = (const uint4*)os;       // 128 d x 8 uint4
#pragma unroll
    for (int p = 0; p < 2; p++) {
        int idx = tid + p * 512;
        int dlw = idx >> 3, u = idx & 7;
        *(uint4*)&out[(size_t)(d0 + dlw) * (Hn * Ln) + h * Ln + u * 8] = os4[dlw * 8 + u];
    }
}

// ---------------- bqk: warp-per-output (1024 outputs) --------------------------------
__global__ void __launch_bounds__(256) bqk2(const float* __restrict__ bq,
                                            const float* __restrict__ Wkr,
                                            float* __restrict__ out)
{
    const int lane = threadIdx.x & 31, w = threadIdx.x >> 5;
    const int hl = blockIdx.x * 8 + w;           // 128 blocks x 8 warps = 1024
    const int h = hl >> 6, l = hl & 63;
    float s = 0.f;
#pragma unroll
    for (int i = 0; i < 4; i++) {
        int dk = lane * 4 + i;
        s = fmaf(bq[h * DKn + dk], Wkr[l * DKn + dk], s);
    }
#pragma unroll
    for (int o = 16; o >= 1; o >>= 1)
        s += __shfl_xor_sync(0xffffffffu, s, o);
    if (lane == 0) out[hl] = s;
}

// ================= fp16 tensor-core GEMM =================
#define HST 36864   // bytes per stage (A 18432 + B 18432)

struct HArgs {
    const __half* A[3];
    const __half* BT[3];
    const float*  bias[3];
    void*         C[3];
    int           mode[3];   // 0 plain f32 out, 1 latent remap f16, 2 latent transposed f16
    float         presc[3];
};

__global__ void __launch_bounds__(256, 2) hgemm(HArgs ga, int N, int K)
{
    extern __shared__ char smc[];
    const int z = blockIdx.z;
    const __half* __restrict__ A    = ga.A[z];
    const __half* __restrict__ BT   = ga.BT[z];
    const float*  __restrict__ bias = ga.bias[z];
    const int   mode  = ga.mode[z];
    const float presc = ga.presc[z];

    const int tid  = threadIdx.x;
    const int lane = tid & 31, wid = tid >> 5;
    const int wm = wid & 3, wn = wid >> 2;
    const int g  = lane >> 2, tg = lane & 3;
    const int r8 = lane & 7, rh = (lane >> 3) & 1, ch = (lane >> 4) & 1;

    const uint32_t smb = (uint32_t)__cvta_generic_to_shared(smc);
    const uint32_t aFrag = smb + (wm * 32 + r8 + rh * 8) * 144 + ch * 16;
    const uint32_t bFrag = smb + 18432 + (wn * 64 + r8 + rh * 8) * 144 + ch * 16;

    const int lrow = tid >> 3;
    const int lcol = (tid & 7) * 8;
    const __half* Ab  = A  + (size_t)(blockIdx.y * 128) * K;
    const __half* BTb = BT + (size_t)(blockIdx.x * 128) * K;

    float acc[2][8][4];
#pragma unroll
    for (int i = 0; i < 2; i++)
#pragma unroll
        for (int j = 0; j < 8; j++)
#pragma unroll
            for (int v = 0; v < 4; v++) acc[i][j][v] = 0.f;

    const int NKB = K / 64;
    {
#pragma unroll
        for (int p = 0; p < 4; p++) {
            int row = lrow + 32 * p;
            CPA16(smb + row * 144 + lcol * 2, Ab + (size_t)row * K + lcol);
            CPA16(smb + 18432 + row * 144 + lcol * 2, BTb + (size_t)row * K + lcol);
        }
        asm volatile("cp.async.commit_group;\n");
    }

    int buf = 0;
    for (int kb = 0; kb < NKB; kb++) {
        if (kb + 1 < NKB) {
            const int k0 = (kb + 1) * 64;
            const uint32_t so = (buf ^ 1) * HST;
#pragma unroll
            for (int p = 0; p < 4; p++) {
                int row = lrow + 32 * p;
                CPA16(smb + so + row * 144 + lcol * 2, Ab + (size_t)row * K + k0 + lcol);
                CPA16(smb + so + 18432 + row * 144 + lcol * 2,
                      BTb + (size_t)row * K + k0 + lcol);
            }
        }
        asm volatile("cp.async.commit_group;\n");
        asm volatile("cp.async.wait_group 1;\n");
        __syncthreads();

        const uint32_t af = aFrag + buf * HST;
        const uint32_t bf = bFrag + buf * HST;
#pragma unroll
        for (int kk = 0; kk < 4; kk++) {
            uint32_t a0[4], a1[4];
            ldsm4(a0, af + kk * 32);
            ldsm4(a1, af + 16 * 144 + kk * 32);
#pragma unroll
            for (int ntp = 0; ntp < 4; ntp++) {
                uint32_t bb[4];
                ldsm4(bb, bf + ntp * 16 * 144 + kk * 32);
                mma_f16(acc[0][2*ntp],   a0, bb[0], bb[2]);
                mma_f16(acc[0][2*ntp+1], a0, bb[1], bb[3]);
                mma_f16(acc[1][2*ntp],   a1, bb[0], bb[2]);
                mma_f16(acc[1][2*ntp+1], a1, bb[1], bb[3]);
            }
        }
        __syncthreads();
        buf ^= 1;
    }

    if (mode == 2) {
        float* Tr = (float*)smc;   // [128][132]
        __half* C = (__half*)ga.C[z];
#pragma unroll
        for (int mi = 0; mi < 2; mi++) {
#pragma unroll
            for (int nt = 0; nt < 8; nt++) {
                int r0 = wm * 32 + mi * 16 + g;
                int c  = wn * 64 + nt * 8 + 2 * tg;
                int cg = blockIdx.x * 128 + c;
                float b0 = bias[cg], b1 = bias[cg + 1];
                Tr[r0 * 132 + c]       = acc[mi][nt][0] + b0;
                Tr[r0 * 132 + c + 1]   = acc[mi][nt][1] + b1;
                Tr[(r0+8) * 132 + c]   = acc[mi][nt][2] + b0;
                Tr[(r0+8) * 132 + c+1] = acc[mi][nt][3] + b1;
            }
        }
        __syncthreads();
#pragma unroll
        for (int cc = 0; cc < 16; cc++) {
            int c  = wid * 16 + cc;
            int cg = blockIdx.x * 128 + c;
            int h = cg >> 6, l = cg & 63;
            int sg = blockIdx.y * 128 + lane * 4;
            int b = sg >> 11, s = sg & 2047;
            __half2 h0 = __floats2half2_rn(Tr[(lane*4+0) * 132 + c],
                                           Tr[(lane*4+1) * 132 + c]);
            __half2 h1 = __floats2half2_rn(Tr[(lane*4+2) * 132 + c],
                                           Tr[(lane*4+3) * 132 + c]);
            uint2 o; o.x = *(uint32_t*)&h0; o.y = *(uint32_t*)&h1;
            *(uint2*)&C[((size_t)((b * Hn + h) * Ln + l)) * Sn + s] = o;
        }
        return;
    }

    const int rowb = blockIdx.y * 128 + wm * 32 + g;
    const int colb = blockIdx.x * 128 + wn * 64 + 2 * tg;
#pragma unroll
    for (int mi = 0; mi < 2; mi++) {
#pragma unroll
        for (int nt = 0; nt < 8; nt++) {
            const int col = colb + nt * 8;
            const float bv0 = bias[col], bv1 = bias[col + 1];
            const int r0 = rowb + mi * 16;
            const int r1 = r0 + 8;
            float2 v0 = make_float2(acc[mi][nt][0] + bv0, acc[mi][nt][1] + bv1);
            float2 v1 = make_float2(acc[mi][nt][2] + bv0, acc[mi][nt][3] + bv1);
            if (mode == 1) {
                __half* C = (__half*)ga.C[z];
                __half2 h0 = __floats2half2_rn(v0.x * presc, v0.y * presc);
                __half2 h1 = __floats2half2_rn(v1.x * presc, v1.y * presc);
                const int h = col >> 6, l = col & 63;
                {
                    const int b = r0 >> 11, s = r0 & 2047;
                    *(__half2*)&C[(((size_t)(b * Hn + h) * Sn + s) << 6) + l] = h0;
                }
                {
                    const int b = r1 >> 11, s = r1 & 2047;
                    *(__half2*)&C[(((size_t)(b * Hn + h) * Sn + s) << 6) + l] = h1;
                }
            } else {
                float* C = (float*)ga.C[z];
                *(float2*)&C[(size_t)r0 * N + col] = v0;
                *(float2*)&C[(size_t)r1 * N + col] = v1;
            }
        }
    }
}

// ================= fp16 tensor-core flash attention (latent d=64, causal) ============
#define QSB 0
#define PSB 18432
#define KSB 36864
#define VSB 46080
#define FSMEM 55296

__global__ void __launch_bounds__(128, 2) flash_tc(
    const __half* __restrict__ Q, const __half* __restrict__ Kl,
    const __half* __restrict__ VT, __half* __restrict__ O)
{
    extern __shared__ char smc[];
    __half* smh = (__half*)smc;

    const int tid  = threadIdx.x;
    const int lane = tid & 31, wid = tid >> 5;
    const int g = lane >> 2, tg = lane & 3;
    const int r8 = lane & 7, rh = (lane >> 3) & 1, ch = (lane >> 4) & 1;

    const int qt = gridDim.x - 1 - blockIdx.x;
    const int bh = blockIdx.y;
    const int q0 = qt * 128;

    const __half* Qg = Q  + ((size_t)bh * Sn + q0) * Ln;
    const __half* Kg = Kl + (size_t)bh * Sn * Ln;
    const __half* Vg = VT + (size_t)bh * Ln * Sn;

    const uint32_t smb = (uint32_t)__cvta_generic_to_shared(smc);
    const uint32_t qAddr = smb + QSB + (wid * 32 + r8 + rh * 8) * 144 + ch * 16;
    const uint32_t pAddr = smb + PSB + (wid * 32 + r8 + rh * 8) * 144 + ch * 16;
    const uint32_t kFrag = smb + KSB + (r8 + rh * 8) * 144 + ch * 16;
    const uint32_t vFrag = smb + VSB + (r8 + rh * 8) * 144 + ch * 16;

#pragma unroll
    for (int i = 0; i < 8; i++) {
        int idx = tid + i * 128;
        int row = idx >> 3, c = (idx & 7) * 8;
        CPA16(smb + QSB + row * 144 + c * 2, Qg + (size_t)row * 64 + c);
    }
#pragma unroll
    for (int i = 0; i < 4; i++) {
        int idx = tid + i * 128;
        int row = idx >> 3, c = (idx & 7) * 8;
        CPA16(smb + KSB + row * 144 + c * 2, Kg + (size_t)row * 64 + c);
        CPA16(smb + VSB + row * 144 + c * 2, Vg + (size_t)row * Sn + c);
    }
    asm volatile("cp.async.commit_group;\n");

    float oacc[2][8][4];
    float mrow[2][2], lrow2[2][2];
#pragma unroll
    for (int mi = 0; mi < 2; mi++) {
        mrow[mi][0] = mrow[mi][1] = -1e30f;
        lrow2[mi][0] = lrow2[mi][1] = 0.f;
#pragma unroll
        for (int nt = 0; nt < 8; nt++)
#pragma unroll
            for (int v = 0; v < 4; v++) oacc[mi][nt][v] = 0.f;
    }

    const int ktmax = 2 * qt + 2;
    for (int kt = 0; kt < ktmax; kt++) {
        asm volatile("cp.async.wait_group 0;\n");
        __syncthreads();

        float sacc[2][8][4];
#pragma unroll
        for (int mi = 0; mi < 2; mi++)
#pragma unroll
            for (int nt = 0; nt < 8; nt++)
#pragma unroll
                for (int v = 0; v < 4; v++) sacc[mi][nt][v] = 0.f;

#pragma unroll
        for (int kk = 0; kk < 4; kk++) {
            uint32_t qa[2][4];
            ldsm4(qa[0], qAddr + kk * 32);
            ldsm4(qa[1], qAddr + 16 * 144 + kk * 32);
#pragma unroll
            for (int ntp = 0; ntp < 4; ntp++) {
                uint32_t kb[4];
                ldsm4(kb, kFrag + ntp * 16 * 144 + kk * 32);
                mma_f16(sacc[0][2*ntp],   qa[0], kb[0], kb[2]);
                mma_f16(sacc[0][2*ntp+1], qa[0], kb[1], kb[3]);
                mma_f16(sacc[1][2*ntp],   qa[1], kb[0], kb[2]);
                mma_f16(sacc[1][2*ntp+1], qa[1], kb[1], kb[3]);
            }
        }

        if (kt >= 2 * qt) {
            const int colb = kt * 64 + 2 * tg;
#pragma unroll
            for (int mi = 0; mi < 2; mi++) {
                const int rb = q0 + wid * 32 + mi * 16 + g;
#pragma unroll
                for (int nt = 0; nt < 8; nt++) {
                    const int c = colb + 8 * nt;
                    if (c     > rb)     sacc[mi][nt][0] = -1e30f;
                    if (c + 1 > rb)     sacc[mi][nt][1] = -1e30f;
                    if (c     > rb + 8) sacc[mi][nt][2] = -1e30f;
                    if (c + 1 > rb + 8) sacc[mi][nt][3] = -1e30f;
                }
            }
        }

#pragma unroll
        for (int mi = 0; mi < 2; mi++) {
#pragma unroll
            for (int hh = 0; hh < 2; hh++) {
                float rm = -1e30f;
#pragma unroll
                for (int nt = 0; nt < 8; nt++)
                    rm = fmaxf(rm, fmaxf(sacc[mi][nt][2*hh], sacc[mi][nt][2*hh+1]));
                rm = fmaxf(rm, __shfl_xor_sync(0xffffffffu, rm, 1));
                rm = fmaxf(rm, __shfl_xor_sync(0xffffffffu, rm, 2));
                float mo = mrow[mi][hh];
                float mn = fmaxf(mo, rm);
                float fac = exp2f(mo - mn);
                float rs = 0.f;
                const int prow = wid * 32 + mi * 16 + hh * 8 + g;
#pragma unroll
                for (int nt = 0; nt < 8; nt++) {
                    float p0 = exp2f(sacc[mi][nt][2*hh]   - mn);
                    float p1 = exp2f(sacc[mi][nt][2*hh+1] - mn);
                    rs += p0 + p1;
                    __half2 hp = __floats2half2_rn(p0, p1);
                    *(__half2*)&smh[PSB / 2 + prow * 72 + nt * 8 + 2 * tg] = hp;
                    oacc[mi][nt][2*hh]   *= fac;
                    oacc[mi][nt][2*hh+1] *= fac;
                }
                rs += __shfl_xor_sync(0xffffffffu, rs, 1);
                rs += __shfl_xor_sync(0xffffffffu, rs, 2);
                lrow2[mi][hh] = lrow2[mi][hh] * fac + rs;
                mrow[mi][hh] = mn;
            }
        }
        __syncwarp();

#pragma unroll
        for (int kk = 0; kk < 4; kk++) {
            uint32_t pa[2][4];
            ldsm4(pa[0], pAddr + kk * 32);
            ldsm4(pa[1], pAddr + 16 * 144 + kk * 32);
#pragma unroll
            for (int ntp = 0; ntp < 4; ntp++) {
                uint32_t vb[4];
                ldsm4(vb, vFrag + ntp * 16 * 144 + kk * 32);
                mma_f16(oacc[0][2*ntp],   pa[0], vb[0], vb[2]);
                mma_f16(oacc[0][2*ntp+1], pa[0], vb[1], vb[3]);
                mma_f16(oacc[1][2*ntp],   pa[1], vb[0], vb[2]);
                mma_f16(oacc[1][2*ntp+1], pa[1], vb[1], vb[3]);
            }
        }

        __syncthreads();
        if (kt + 1 < ktmax) {
            const int kbase = (kt + 1) * 64;
#pragma unroll
            for (int i = 0; i < 4; i++) {
                int idx = tid + i * 128;
                int row = idx >> 3, c = (idx & 7) * 8;
                CPA16(smb + KSB + row * 144 + c * 2,
                      Kg + (size_t)(kbase + row) * 64 + c);
                CPA16(smb + VSB + row * 144 + c * 2,
                      Vg + (size_t)row * Sn + kbase + c);
            }
        }
        asm volatile("cp.async.commit_group;\n");
    }

    const int b = bh >> 4, h = bh & 15;
#pragma unroll
    for (int mi = 0; mi < 2; mi++) {
#pragma unroll
        for (int hh = 0; hh < 2; hh++) {
            float inv = 1.0f / lrow2[mi][hh];
            int row = q0 + wid * 32 + mi * 16 + hh * 8 + g;
            __half* o = O + ((size_t)(b * Sn + row)) * (Hn * Ln) + h * Ln + 2 * tg;
#pragma unroll
            for (int nt = 0; nt < 8; nt++) {
                __half2 hv = __floats2half2_rn(oacc[mi][nt][2*hh] * inv,
                                               oacc[mi][nt][2*hh+1] * inv);
                *(__half2*)&o[nt * 8] = hv;
            }
        }
    }
}

// ---------------- launch ----------------
extern "C" void kernel_launch(void* const* d_in, const int* in_sizes, int n_in,
                              void* d_out, int out_size)
{
    (void)in_sizes; (void)n_in; (void)out_size;
    const float* queries = (const float*)d_in[0];
    const float* keys    = (const float*)d_in[1];
    const float* values  = (const float*)d_in[2];
    const float* Wq      = (const float*)d_in[3];
    const float* bq      = (const float*)d_in[4];
    const float* Wlk     = (const float*)d_in[5];
    const float* blk     = (const float*)d_in[6];
    const float* Wlv     = (const float*)d_in[7];
    const float* blv     = (const float*)d_in[8];
    const float* Wkr     = (const float*)d_in[9];
    const float* Wvr     = (const float*)d_in[10];
    const float* Wout    = (const float*)d_in[11];
    const float* bout    = (const float*)d_in[12];
    float* out = (float*)d_out;

    __half *wqkT, *wvoT, *wlkT, *wlvT, *qh, *kh, *vh, *q, *lk, *lvT, *olat;
    float *bqk;
    cudaGetSymbolAddress((void**)&wqkT, g_wqkT);
    cudaGetSymbolAddress((void**)&bqk,  g_bqk);
    cudaGetSymbolAddress((void**)&wvoT, g_wvoT);
    cudaGetSymbolAddress((void**)&wlkT, g_wlkT);
    cudaGetSymbolAddress((void**)&wlvT, g_wlvT);
    cudaGetSymbolAddress((void**)&qh,   g_qh);
    cudaGetSymbolAddress((void**)&kh,   g_kh);
    cudaGetSymbolAddress((void**)&vh,   g_vh);
    cudaGetSymbolAddress((void**)&q,    g_q);
    cudaGetSymbolAddress((void**)&lk,   g_lk);
    cudaGetSymbolAddress((void**)&lvT,  g_lvT);
    cudaGetSymbolAddress((void**)&olat, g_olat);

    const int gemm_smem = 2 * HST;   // 73728 B
    const int wsmem = (WQS_F + WKT_F) * 4 + 64 * 128 * 2;  // 117248 B
    cudaFuncSetAttribute(hgemm, cudaFuncAttributeMaxDynamicSharedMemorySize, gemm_smem);
    cudaFuncSetAttribute(flash_tc, cudaFuncAttributeMaxDynamicSharedMemorySize, FSMEM);
    cudaFuncSetAttribute(wqk3, cudaFuncAttributeMaxDynamicSharedMemorySize, wsmem);
    cudaFuncSetAttribute(wvo3, cudaFuncAttributeMaxDynamicSharedMemorySize, wsmem);

    // convert activations to fp16
    RArgs ra;
    ra.in[0] = (const float4*)queries; ra.out[0] = (uint4*)qh;
    ra.in[1] = (const float4*)keys;    ra.out[1] = (uint4*)kh;
    ra.in[2] = (const float4*)values;  ra.out[2] = (uint4*)vh;
    const int n8 = Bn * Sn * Dn / 8;
    roundcp<<<dim3((n8 + 255) / 256, 3), 256>>>(ra, n8);

    // weights
    wtrans<<<dim3(64, 32), 256>>>(Wlk, wlkT);
    wtrans<<<dim3(64, 32), 256>>>(Wlv, wlvT);
    wqk3<<<dim3(16, 16), 512, wsmem>>>(Wq, Wkr, wqkT);
    bqk2<<<128, 256>>>(bq, Wkr, bqk);
    wvo3<<<dim3(16, 16), 512, wsmem>>>(Wvr, Wout, wvoT);

    // fused projections: q (scaled f16), lk (f16), lvT (f16 transposed)
    const float presc_q = 1.4426950408889634f / 11.313708498984761f;  // log2e/sqrt(128)
    HArgs pa;
    pa.A[0] = qh; pa.BT[0] = wqkT; pa.bias[0] = bqk; pa.C[0] = q;   pa.mode[0] = 1; pa.presc[0] = presc_q;
    pa.A[1] = kh; pa.BT[1] = wlkT; pa.bias[1] = blk; pa.C[1] = lk;  pa.mode[1] = 1; pa.presc[1] = 1.0f;
    pa.A[2] = vh; pa.BT[2] = wlvT; pa.bias[2] = blv; pa.C[2] = lvT; pa.mode[2] = 2; pa.presc[2] = 1.0f;
    hgemm<<<dim3(8, 32, 3), 256, gemm_smem>>>(pa, 1024, 2048);

    // tensor-core causal latent attention
    flash_tc<<<dim3(Sn / 128, Bn * Hn), 128, FSMEM>>>(q, lk, lvT, olat);

    // output projection
    HArgs po;
    po.A[0] = olat; po.BT[0] = wvoT; po.bias[0] = bout; po.C[0] = out; po.mode[0] = 0; po.presc[0] = 1.0f;
    hgemm<<<dim3(16, 32, 1), 256, gemm_smem>>>(po, 2048, 1024);
}

// round 13
// speedup vs baseline: 1.0219x; 1.0219x over previous
#include <cuda_runtime.h>
#include <cuda_fp16.h>
#include <math.h>
#include <stdint.h>

#define Bn  2
#define Sn  2048
#define Dn  2048
#define Hn  16
#define DKn 128
#define DVn 128
#define Ln  64

// ---------------- scratch (device globals) ----------------
__device__ __half g_wqkT[Hn * Ln * Dn];       // [1024][2048] absorbed Wq^T
__device__ float  g_bqk [Hn * Ln];
__device__ __half g_wvoT[Dn * Hn * Ln];       // [2048][1024] absorbed Wout^T
__device__ __half g_wlkT[Hn * Ln * Dn];       // [1024][2048] Wlk^T
__device__ __half g_wlvT[Hn * Ln * Dn];       // [1024][2048] Wlv^T
__device__ __half g_qh [Bn * Sn * Dn];        // fp16 copies of activations
__device__ __half g_kh [Bn * Sn * Dn];
__device__ __half g_vh [Bn * Sn * Dn];
__device__ __half g_q  [Bn * Hn * Sn * Ln];   // [B,H,S,L], pre-scaled log2e/sqrt(128)
__device__ __half g_lk [Bn * Hn * Sn * Ln];   // [B,H,S,L]
__device__ __half g_lvT[Bn * Hn * Ln * Sn];   // [B,H,L,S]
__device__ __half g_olat[Bn * Sn * Hn * Ln];  // [4096][1024]

// ---------------- helpers ----------------
__device__ __forceinline__ void ldsm4(uint32_t* r, uint32_t a) {
    asm volatile("ldmatrix.sync.aligned.m8n8.x4.shared.b16 {%0,%1,%2,%3}, [%4];"
                 : "=r"(r[0]), "=r"(r[1]), "=r"(r[2]), "=r"(r[3]) : "r"(a));
}
__device__ __forceinline__ void mma_f16(float* c, const uint32_t* a,
                                        uint32_t b0, uint32_t b1) {
    asm volatile(
        "mma.sync.aligned.m16n8k16.row.col.f32.f16.f16.f32 "
        "{%0,%1,%2,%3}, {%4,%5,%6,%7}, {%8,%9}, {%0,%1,%2,%3};\n"
        : "+f"(c[0]), "+f"(c[1]), "+f"(c[2]), "+f"(c[3])
        : "r"(a[0]), "r"(a[1]), "r"(a[2]), "r"(a[3]), "r"(b0), "r"(b1));
}
#define CPA16(dst, src) \
    asm volatile("cp.async.cg.shared.global [%0], [%1], 16;\n" :: "r"(dst), "l"(src))

// ---------------- fp32 -> fp16 conversion pass ----------------
struct RArgs { const float4* in[3]; uint4* out[3]; };
__global__ void __launch_bounds__(256) roundcp(RArgs ra, int n8)
{
    const float4* in = ra.in[blockIdx.y];
    uint4* out = ra.out[blockIdx.y];
    int i = blockIdx.x * 256 + threadIdx.x;
    if (i >= n8) return;
    float4 v0 = in[2 * i], v1 = in[2 * i + 1];
    __half2 h0 = __floats2half2_rn(v0.x, v0.y);
    __half2 h1 = __floats2half2_rn(v0.z, v0.w);
    __half2 h2 = __floats2half2_rn(v1.x, v1.y);
    __half2 h3 = __floats2half2_rn(v1.z, v1.w);
    uint4 o;
    o.x = *(uint32_t*)&h0; o.y = *(uint32_t*)&h1;
    o.z = *(uint32_t*)&h2; o.w = *(uint32_t*)&h3;
    out[i] = o;
}

// ---------------- weight transpose: [2048][1024] f32 -> [1024][2048] f16 ------------
__global__ void __launch_bounds__(256) wtrans(const float* __restrict__ in,
                                              __half* __restrict__ out)
{
    __shared__ float t[32][33];
    int x = threadIdx.x & 31, y = threadIdx.x >> 5;
    int bx = blockIdx.x, by = blockIdx.y;
#pragma unroll
    for (int i = 0; i < 32; i += 8)
        t[y + i][x] = in[(size_t)(bx * 32 + y + i) * 1024 + by * 32 + x];
    __syncthreads();
#pragma unroll
    for (int i = 0; i < 32; i += 8)
        out[(size_t)(by * 32 + y + i) * 2048 + bx * 32 + x] = __float2half_rn(t[x][y + i]);
}

// ---------------- absorbed weight: wqkT[hl][d] (coalesced, smem-staged, 256 thr) -----
#define WQS_F (128 * 133)
#define WKT_F (128 * 64)
__global__ void __launch_bounds__(256) wqk3(const float* __restrict__ Wq,
                                            const float* __restrict__ Wkr,
                                            __half* __restrict__ out)
{
    extern __shared__ float sm[];
    float* wqs = sm;                       // [128][133]
    float* wkT = sm + WQS_F;               // [128][64]  wkT[dk][l]
    __half* os = (__half*)(sm + WQS_F + WKT_F);  // [64][128]

    const int tid = threadIdx.x;
    const int d0 = blockIdx.x * 128, h = blockIdx.y;

    for (int i = tid; i < Ln * DKn; i += 256) {
        int l = i >> 7, dk = i & 127;
        wkT[dk * 64 + l] = Wkr[i];
    }
#pragma unroll
    for (int p = 0; p < 16; p++) {
        int idx = tid + p * 256;
        int row = idx >> 5, c4 = (idx & 31) * 4;
        float4 v = *(const float4*)(Wq + (size_t)(d0 + row) * Dn + h * DKn + c4);
        float* w = &wqs[row * 133 + c4];
        w[0] = v.x; w[1] = v.y; w[2] = v.z; w[3] = v.w;
    }
    __syncthreads();

    const int dl = tid & 127, lh = tid >> 7;   // lh = 0/1 -> l-range 32
    float s[32];
#pragma unroll
    for (int j = 0; j < 32; j++) s[j] = 0.f;
    for (int dk = 0; dk < DKn; dk++) {
        float a = wqs[dl * 133 + dk];
        const float4* w4 = (const float4*)&wkT[dk * 64 + lh * 32];
#pragma unroll
        for (int jj = 0; jj < 8; jj++) {
            float4 w = w4[jj];
            s[4*jj+0] = fmaf(a, w.x, s[4*jj+0]);
            s[4*jj+1] = fmaf(a, w.y, s[4*jj+1]);
            s[4*jj+2] = fmaf(a, w.z, s[4*jj+2]);
            s[4*jj+3] = fmaf(a, w.w, s[4*jj+3]);
        }
    }
#pragma unroll
    for (int j = 0; j < 32; j++)
        os[(lh * 32 + j) * 128 + dl] = __float2half_rn(s[j]);
    __syncthreads();

    const uint4* os4 = (const uint4*)os;
#pragma unroll
    for (int p = 0; p < 4; p++) {
        int idx = tid + p * 256;
        int l = idx >> 4, u = idx & 15;
        *(uint4*)&out[(size_t)(h * Ln + l) * Dn + d0 + u * 8] = os4[l * 16 + u];
    }
}

// ---------------- absorbed weight: wvoT[d][hl] (coalesced, smem-staged, 256 thr) -----
__global__ void __launch_bounds__(256) wvo3(const float* __restrict__ Wvr,
                                            const float* __restrict__ Wout,
                                            __half* __restrict__ out)
{
    extern __shared__ float sm[];
    float* wos = sm;                       // [128][133]  wos[dv][d_local]
    float* wvT = sm + WQS_F;               // [128][64]   wvT[dv][l]
    __half* os = (__half*)(sm + WQS_F + WKT_F);  // [128][64]

    const int tid = threadIdx.x;
    const int d0 = blockIdx.x * 128, h = blockIdx.y;

    for (int i = tid; i < Ln * DVn; i += 256) {
        int l = i >> 7, dv = i & 127;
        wvT[dv * 64 + l] = Wvr[i];
    }
#pragma unroll
    for (int p = 0; p < 16; p++) {
        int idx = tid + p * 256;
        int dv = idx >> 5, c4 = (idx & 31) * 4;
        float4 v = *(const float4*)(Wout + (size_t)(h * DVn + dv) * Dn + d0 + c4);
        float* w = &wos[dv * 133 + c4];
        w[0] = v.x; w[1] = v.y; w[2] = v.z; w[3] = v.w;
    }
    __syncthreads();

    const int dl = tid & 127, lh = tid >> 7;
    float s[32];
#pragma unroll
    for (int j = 0; j < 32; j++) s[j] = 0.f;
    for (int dv = 0; dv < DVn; dv++) {
        float a = wos[dv * 133 + dl];
        const float4* w4 = (const float4*)&wvT[dv * 64 + lh * 32];
#pragma unroll
        for (int jj = 0; jj < 8; jj++) {
            float4 w = w4[jj];
            s[4*jj+0] = fmaf(a, w.x, s[4*jj+0]);
            s[4*jj+1] = fmaf(a, w.y, s[4*jj+1]);
            s[4*jj+2] = fmaf(a, w.z, s[4*jj+2]);
            s[4*jj+3] = fmaf(a, w.w, s[4*jj+3]);
        }
    }
#pragma unroll
    for (int j = 0; j < 32; j++)
        os[dl * 64 + lh * 32 + j] = __float2half_rn(s[j]);
    __syncthreads();

    const uint4* os4 = (const uint4*)os;
#pragma unroll
    for (int p = 0; p < 4; p++) {
        int idx = tid + p * 256;
        int dlw = idx >> 3, u = idx & 7;
        *(uint4*)&out[(size_t)(d0 + dlw) * (Hn * Ln) + h * Ln + u * 8] = os4[dlw * 8 + u];
    }
}

// ---------------- bqk: warp-per-output (1024 outputs) --------------------------------
__global__ void __launch_bounds__(256) bqk2(const float* __restrict__ bq,
                                            const float* __restrict__ Wkr,
                                            float* __restrict__ out)
{
    const int lane = threadIdx.x & 31, w = threadIdx.x >> 5;
    const int hl = blockIdx.x * 8 + w;           // 128 blocks x 8 warps = 1024
    const int h = hl >> 6, l = hl & 63;
    float s = 0.f;
#pragma unroll
    for (int i = 0; i < 4; i++) {
        int dk = lane * 4 + i;
        s = fmaf(bq[h * DKn + dk], Wkr[l * DKn + dk], s);
    }
#pragma unroll
    for (int o = 16; o >= 1; o >>= 1)
        s += __shfl_xor_sync(0xffffffffu, s, o);
    if (lane == 0) out[hl] = s;
}

// ================= fp16 tensor-core GEMM =================
#define HST 36864   // bytes per stage (A 18432 + B 18432)

struct HArgs {
    const __half* A[3];
    const __half* BT[3];
    const float*  bias[3];
    void*         C[3];
    int           mode[3];   // 0 plain f32 out, 1 latent remap f16, 2 latent transposed f16
    float         presc[3];
};

__global__ void __launch_bounds__(256, 2) hgemm(HArgs ga, int N, int K)
{
    extern __shared__ char smc[];
    const int z = blockIdx.z;
    const __half* __restrict__ A    = ga.A[z];
    const __half* __restrict__ BT   = ga.BT[z];
    const float*  __restrict__ bias = ga.bias[z];
    const int   mode  = ga.mode[z];
    const float presc = ga.presc[z];

    const int tid  = threadIdx.x;
    const int lane = tid & 31, wid = tid >> 5;
    const int wm = wid & 3, wn = wid >> 2;
    const int g  = lane >> 2, tg = lane & 3;
    const int r8 = lane & 7, rh = (lane >> 3) & 1, ch = (lane >> 4) & 1;

    const uint32_t smb = (uint32_t)__cvta_generic_to_shared(smc);
    const uint32_t aFrag = smb + (wm * 32 + r8 + rh * 8) * 144 + ch * 16;
    const uint32_t bFrag = smb + 18432 + (wn * 64 + r8 + rh * 8) * 144 + ch * 16;

    const int lrow = tid >> 3;
    const int lcol = (tid & 7) * 8;
    const __half* Ab  = A  + (size_t)(blockIdx.y * 128) * K;
    const __half* BTb = BT + (size_t)(blockIdx.x * 128) * K;

    float acc[2][8][4];
#pragma unroll
    for (int i = 0; i < 2; i++)
#pragma unroll
        for (int j = 0; j < 8; j++)
#pragma unroll
            for (int v = 0; v < 4; v++) acc[i][j][v] = 0.f;

    const int NKB = K / 64;
    {
#pragma unroll
        for (int p = 0; p < 4; p++) {
            int row = lrow + 32 * p;
            CPA16(smb + row * 144 + lcol * 2, Ab + (size_t)row * K + lcol);
            CPA16(smb + 18432 + row * 144 + lcol * 2, BTb + (size_t)row * K + lcol);
        }
        asm volatile("cp.async.commit_group;\n");
    }

    int buf = 0;
    for (int kb = 0; kb < NKB; kb++) {
        if (kb + 1 < NKB) {
            const int k0 = (kb + 1) * 64;
            const uint32_t so = (buf ^ 1) * HST;
#pragma unroll
            for (int p = 0; p < 4; p++) {
                int row = lrow + 32 * p;
                CPA16(smb + so + row * 144 + lcol * 2, Ab + (size_t)row * K + k0 + lcol);
                CPA16(smb + so + 18432 + row * 144 + lcol * 2,
                      BTb + (size_t)row * K + k0 + lcol);
            }
        }
        asm volatile("cp.async.commit_group;\n");
        asm volatile("cp.async.wait_group 1;\n");
        __syncthreads();

        const uint32_t af = aFrag + buf * HST;
        const uint32_t bf = bFrag + buf * HST;
#pragma unroll
        for (int kk = 0; kk < 4; kk++) {
            uint32_t a0[4], a1[4];
            ldsm4(a0, af + kk * 32);
            ldsm4(a1, af + 16 * 144 + kk * 32);
#pragma unroll
            for (int ntp = 0; ntp < 4; ntp++) {
                uint32_t bb[4];
                ldsm4(bb, bf + ntp * 16 * 144 + kk * 32);
                mma_f16(acc[0][2*ntp],   a0, bb[0], bb[2]);
                mma_f16(acc[0][2*ntp+1], a0, bb[1], bb[3]);
                mma_f16(acc[1][2*ntp],   a1, bb[0], bb[2]);
                mma_f16(acc[1][2*ntp+1], a1, bb[1], bb[3]);
            }
        }
        __syncthreads();
        buf ^= 1;
    }

    if (mode == 2) {
        float* Tr = (float*)smc;   // [128][132]
        __half* C = (__half*)ga.C[z];
#pragma unroll
        for (int mi = 0; mi < 2; mi++) {
#pragma unroll
            for (int nt = 0; nt < 8; nt++) {
                int r0 = wm * 32 + mi * 16 + g;
                int c  = wn * 64 + nt * 8 + 2 * tg;
                int cg = blockIdx.x * 128 + c;
                float b0 = bias[cg], b1 = bias[cg + 1];
                Tr[r0 * 132 + c]       = acc[mi][nt][0] + b0;
                Tr[r0 * 132 + c + 1]   = acc[mi][nt][1] + b1;
                Tr[(r0+8) * 132 + c]   = acc[mi][nt][2] + b0;
                Tr[(r0+8) * 132 + c+1] = acc[mi][nt][3] + b1;
            }
        }
        __syncthreads();
#pragma unroll
        for (int cc = 0; cc < 16; cc++) {
            int c  = wid * 16 + cc;
            int cg = blockIdx.x * 128 + c;
            int h = cg >> 6, l = cg & 63;
            int sg = blockIdx.y * 128 + lane * 4;
            int b = sg >> 11, s = sg & 2047;
            __half2 h0 = __floats2half2_rn(Tr[(lane*4+0) * 132 + c],
                                           Tr[(lane*4+1) * 132 + c]);
            __half2 h1 = __floats2half2_rn(Tr[(lane*4+2) * 132 + c],
                                           Tr[(lane*4+3) * 132 + c]);
            uint2 o; o.x = *(uint32_t*)&h0; o.y = *(uint32_t*)&h1;
            *(uint2*)&C[((size_t)((b * Hn + h) * Ln + l)) * Sn + s] = o;
        }
        return;
    }

    const int rowb = blockIdx.y * 128 + wm * 32 + g;
    const int colb = blockIdx.x * 128 + wn * 64 + 2 * tg;
#pragma unroll
    for (int mi = 0; mi < 2; mi++) {
#pragma unroll
        for (int nt = 0; nt < 8; nt++) {
            const int col = colb + nt * 8;
            const float bv0 = bias[col], bv1 = bias[col + 1];
            const int r0 = rowb + mi * 16;
            const int r1 = r0 + 8;
            float2 v0 = make_float2(acc[mi][nt][0] + bv0, acc[mi][nt][1] + bv1);
            float2 v1 = make_float2(acc[mi][nt][2] + bv0, acc[mi][nt][3] + bv1);
            if (mode == 1) {
                __half* C = (__half*)ga.C[z];
                __half2 h0 = __floats2half2_rn(v0.x * presc, v0.y * presc);
                __half2 h1 = __floats2half2_rn(v1.x * presc, v1.y * presc);
                const int h = col >> 6, l = col & 63;
                {
                    const int b = r0 >> 11, s = r0 & 2047;
                    *(__half2*)&C[(((size_t)(b * Hn + h) * Sn + s) << 6) + l] = h0;
                }
                {
                    const int b = r1 >> 11, s = r1 & 2047;
                    *(__half2*)&C[(((size_t)(b * Hn + h) * Sn + s) << 6) + l] = h1;
                }
            } else {
                float* C = (float*)ga.C[z];
                *(float2*)&C[(size_t)r0 * N + col] = v0;
                *(float2*)&C[(size_t)r1 * N + col] = v1;
            }
        }
    }
}

// ================= fp16 flash attention, double-buffered K/V ============
#define QSB 0
#define PSB 18432
#define KSB 36864
#define VSB 46080
#define KVST 18432           // stride between K/V stage pairs
#define FSMEM 73728

__global__ void __launch_bounds__(128, 2) flash_tc(
    const __half* __restrict__ Q, const __half* __restrict__ Kl,
    const __half* __restrict__ VT, __half* __restrict__ O)
{
    extern __shared__ char smc[];
    __half* smh = (__half*)smc;

    const int tid  = threadIdx.x;
    const int lane = tid & 31, wid = tid >> 5;
    const int g = lane >> 2, tg = lane & 3;
    const int r8 = lane & 7, rh = (lane >> 3) & 1, ch = (lane >> 4) & 1;

    const int qt = gridDim.x - 1 - blockIdx.x;
    const int bh = blockIdx.y;
    const int q0 = qt * 128;

    const __half* Qg = Q  + ((size_t)bh * Sn + q0) * Ln;
    const __half* Kg = Kl + (size_t)bh * Sn * Ln;
    const __half* Vg = VT + (size_t)bh * Ln * Sn;

    const uint32_t smb = (uint32_t)__cvta_generic_to_shared(smc);
    const uint32_t qAddr = smb + QSB + (wid * 32 + r8 + rh * 8) * 144 + ch * 16;
    const uint32_t pAddr = smb + PSB + (wid * 32 + r8 + rh * 8) * 144 + ch * 16;
    const uint32_t kFrag = smb + KSB + (r8 + rh * 8) * 144 + ch * 16;
    const uint32_t vFrag = smb + VSB + (r8 + rh * 8) * 144 + ch * 16;

    // prologue: Q + K/V tile 0 -> stage 0
#pragma unroll
    for (int i = 0; i < 8; i++) {
        int idx = tid + i * 128;
        int row = idx >> 3, c = (idx & 7) * 8;
        CPA16(smb + QSB + row * 144 + c * 2, Qg + (size_t)row * 64 + c);
    }
#pragma unroll
    for (int i = 0; i < 4; i++) {
        int idx = tid + i * 128;
        int row = idx >> 3, c = (idx & 7) * 8;
        CPA16(smb + KSB + row * 144 + c * 2, Kg + (size_t)row * 64 + c);
        CPA16(smb + VSB + row * 144 + c * 2, Vg + (size_t)row * Sn + c);
    }
    asm volatile("cp.async.commit_group;\n");

    float oacc[2][8][4];
    float mrow[2][2], lrow2[2][2];
#pragma unroll
    for (int mi = 0; mi < 2; mi++) {
        mrow[mi][0] = mrow[mi][1] = -1e30f;
        lrow2[mi][0] = lrow2[mi][1] = 0.f;
#pragma unroll
        for (int nt = 0; nt < 8; nt++)
#pragma unroll
            for (int v = 0; v < 4; v++) oacc[mi][nt][v] = 0.f;
    }

    const int ktmax = 2 * qt + 2;
    for (int kt = 0; kt < ktmax; kt++) {
        // prefetch kt+1 into the other stage (overlaps with this iteration's compute)
        if (kt + 1 < ktmax) {
            const int kbase = (kt + 1) * 64;
            const uint32_t so = ((kt + 1) & 1) * KVST;
#pragma unroll
            for (int i = 0; i < 4; i++) {
                int idx = tid + i * 128;
                int row = idx >> 3, c = (idx & 7) * 8;
                CPA16(smb + KSB + so + row * 144 + c * 2,
                      Kg + (size_t)(kbase + row) * 64 + c);
                CPA16(smb + VSB + so + row * 144 + c * 2,
                      Vg + (size_t)row * Sn + kbase + c);
            }
        }
        asm volatile("cp.async.commit_group;\n");
        asm volatile("cp.async.wait_group 1;\n");
        __syncthreads();

        const uint32_t kF = kFrag + (kt & 1) * KVST;
        const uint32_t vF = vFrag + (kt & 1) * KVST;

        // ---- S = Q @ K^T ----
        float sacc[2][8][4];
#pragma unroll
        for (int mi = 0; mi < 2; mi++)
#pragma unroll
            for (int nt = 0; nt < 8; nt++)
#pragma unroll
                for (int v = 0; v < 4; v++) sacc[mi][nt][v] = 0.f;

#pragma unroll
        for (int kk = 0; kk < 4; kk++) {
            uint32_t qa[2][4];
            ldsm4(qa[0], qAddr + kk * 32);
            ldsm4(qa[1], qAddr + 16 * 144 + kk * 32);
#pragma unroll
            for (int ntp = 0; ntp < 4; ntp++) {
                uint32_t kb[4];
                ldsm4(kb, kF + ntp * 16 * 144 + kk * 32);
                mma_f16(sacc[0][2*ntp],   qa[0], kb[0], kb[2]);
                mma_f16(sacc[0][2*ntp+1], qa[0], kb[1], kb[3]);
                mma_f16(sacc[1][2*ntp],   qa[1], kb[0], kb[2]);
                mma_f16(sacc[1][2*ntp+1], qa[1], kb[1], kb[3]);
            }
        }

        if (kt >= 2 * qt) {
            const int colb = kt * 64 + 2 * tg;
#pragma unroll
            for (int mi = 0; mi < 2; mi++) {
                const int rb = q0 + wid * 32 + mi * 16 + g;
#pragma unroll
                for (int nt = 0; nt < 8; nt++) {
                    const int c = colb + 8 * nt;
                    if (c     > rb)     sacc[mi][nt][0] = -1e30f;
                    if (c + 1 > rb)     sacc[mi][nt][1] = -1e30f;
                    if (c     > rb + 8) sacc[mi][nt][2] = -1e30f;
                    if (c + 1 > rb + 8) sacc[mi][nt][3] = -1e30f;
                }
            }
        }

        // ---- online softmax (log2 units) ----
#pragma unroll
        for (int mi = 0; mi < 2; mi++) {
#pragma unroll
            for (int hh = 0; hh < 2; hh++) {
                float rm = -1e30f;
#pragma unroll
                for (int nt = 0; nt < 8; nt++)
                    rm = fmaxf(rm, fmaxf(sacc[mi][nt][2*hh], sacc[mi][nt][2*hh+1]));
                rm = fmaxf(rm, __shfl_xor_sync(0xffffffffu, rm, 1));
                rm = fmaxf(rm, __shfl_xor_sync(0xffffffffu, rm, 2));
                float mo = mrow[mi][hh];
                float mn = fmaxf(mo, rm);
                float fac = exp2f(mo - mn);
                float rs = 0.f;
                const int prow = wid * 32 + mi * 16 + hh * 8 + g;
#pragma unroll
                for (int nt = 0; nt < 8; nt++) {
                    float p0 = exp2f(sacc[mi][nt][2*hh]   - mn);
                    float p1 = exp2f(sacc[mi][nt][2*hh+1] - mn);
                    rs += p0 + p1;
                    __half2 hp = __floats2half2_rn(p0, p1);
                    *(__half2*)&smh[PSB / 2 + prow * 72 + nt * 8 + 2 * tg] = hp;
                    oacc[mi][nt][2*hh]   *= fac;
                    oacc[mi][nt][2*hh+1] *= fac;
                }
                rs += __shfl_xor_sync(0xffffffffu, rs, 1);
                rs += __shfl_xor_sync(0xffffffffu, rs, 2);
                lrow2[mi][hh] = lrow2[mi][hh] * fac + rs;
                mrow[mi][hh] = mn;
            }
        }
        __syncwarp();

        // ---- O += P @ V ----
#pragma unroll
        for (int kk = 0; kk < 4; kk++) {
            uint32_t pa[2][4];
            ldsm4(pa[0], pAddr + kk * 32);
            ldsm4(pa[1], pAddr + 16 * 144 + kk * 32);
#pragma unroll
            for (int ntp = 0; ntp < 4; ntp++) {
                uint32_t vb[4];
                ldsm4(vb, vF + ntp * 16 * 144 + kk * 32);
                mma_f16(oacc[0][2*ntp],   pa[0], vb[0], vb[2]);
                mma_f16(oacc[0][2*ntp+1], pa[0], vb[1], vb[3]);
                mma_f16(oacc[1][2*ntp],   pa[1], vb[0], vb[2]);
                mma_f16(oacc[1][2*ntp+1], pa[1], vb[1], vb[3]);
            }
        }
        __syncthreads();
    }

    // ---- write O (f16, [4096][1024]) ----
    const int b = bh >> 4, h = bh & 15;
#pragma unroll
    for (int mi = 0; mi < 2; mi++) {
#pragma unroll
        for (int hh = 0; hh < 2; hh++) {
            float inv = 1.0f / lrow2[mi][hh];
            int row = q0 + wid * 32 + mi * 16 + hh * 8 + g;
            __half* o = O + ((size_t)(b * Sn + row)) * (Hn * Ln) + h * Ln + 2 * tg;
#pragma unroll
            for (int nt = 0; nt < 8; nt++) {
                __half2 hv = __floats2half2_rn(oacc[mi][nt][2*hh] * inv,
                                               oacc[mi][nt][2*hh+1] * inv);
                *(__half2*)&o[nt * 8] = hv;
            }
        }
    }
}

// ---------------- launch ----------------
extern "C" void kernel_launch(void* const* d_in, const int* in_sizes, int n_in,
                              void* d_out, int out_size)
{
    (void)in_sizes; (void)n_in; (void)out_size;
    const float* queries = (const float*)d_in[0];
    const float* keys    = (const float*)d_in[1];
    const float* values  = (const float*)d_in[2];
    const float* Wq      = (const float*)d_in[3];
    const float* bq      = (const float*)d_in[4];
    const float* Wlk     = (const float*)d_in[5];
    const float* blk     = (const float*)d_in[6];
    const float* Wlv     = (const float*)d_in[7];
    const float* blv     = (const float*)d_in[8];
    const float* Wkr     = (const float*)d_in[9];
    const float* Wvr     = (const float*)d_in[10];
    const float* Wout    = (const float*)d_in[11];
    const float* bout    = (const float*)d_in[12];
    float* out = (float*)d_out;

    __half *wqkT, *wvoT, *wlkT, *wlvT, *qh, *kh, *vh, *q, *lk, *lvT, *olat;
    float *bqk;
    cudaGetSymbolAddress((void**)&wqkT, g_wqkT);
    cudaGetSymbolAddress((void**)&bqk,  g_bqk);
    cudaGetSymbolAddress((void**)&wvoT, g_wvoT);
    cudaGetSymbolAddress((void**)&wlkT, g_wlkT);
    cudaGetSymbolAddress((void**)&wlvT, g_wlvT);
    cudaGetSymbolAddress((void**)&qh,   g_qh);
    cudaGetSymbolAddress((void**)&kh,   g_kh);
    cudaGetSymbolAddress((void**)&vh,   g_vh);
    cudaGetSymbolAddress((void**)&q,    g_q);
    cudaGetSymbolAddress((void**)&lk,   g_lk);
    cudaGetSymbolAddress((void**)&lvT,  g_lvT);
    cudaGetSymbolAddress((void**)&olat, g_olat);

    const int gemm_smem = 2 * HST;   // 73728 B
    const int wsmem = (WQS_F + WKT_F) * 4 + 64 * 128 * 2;  // 117248 B
    cudaFuncSetAttribute(hgemm, cudaFuncAttributeMaxDynamicSharedMemorySize, gemm_smem);
    cudaFuncSetAttribute(flash_tc, cudaFuncAttributeMaxDynamicSharedMemorySize, FSMEM);
    cudaFuncSetAttribute(wqk3, cudaFuncAttributeMaxDynamicSharedMemorySize, wsmem);
    cudaFuncSetAttribute(wvo3, cudaFuncAttributeMaxDynamicSharedMemorySize, wsmem);

    // convert activations to fp16
    RArgs ra;
    ra.in[0] = (const float4*)queries; ra.out[0] = (uint4*)qh;
    ra.in[1] = (const float4*)keys;    ra.out[1] = (uint4*)kh;
    ra.in[2] = (const float4*)values;  ra.out[2] = (uint4*)vh;
    const int n8 = Bn * Sn * Dn / 8;
    roundcp<<<dim3((n8 + 255) / 256, 3), 256>>>(ra, n8);

    // weights
    wtrans<<<dim3(64, 32), 256>>>(Wlk, wlkT);
    wtrans<<<dim3(64, 32), 256>>>(Wlv, wlvT);
    wqk3<<<dim3(16, 16), 256, wsmem>>>(Wq, Wkr, wqkT);
    bqk2<<<128, 256>>>(bq, Wkr, bqk);
    wvo3<<<dim3(16, 16), 256, wsmem>>>(Wvr, Wout, wvoT);

    // fused projections: q (scaled f16), lk (f16), lvT (f16 transposed)
    const float presc_q = 1.4426950408889634f / 11.313708498984761f;  // log2e/sqrt(128)
    HArgs pa;
    pa.A[0] = qh; pa.BT[0] = wqkT; pa.bias[0] = bqk; pa.C[0] = q;   pa.mode[0] = 1; pa.presc[0] = presc_q;
    pa.A[1] = kh; pa.BT[1] = wlkT; pa.bias[1] = blk; pa.C[1] = lk;  pa.mode[1] = 1; pa.presc[1] = 1.0f;
    pa.A[2] = vh; pa.BT[2] = wlvT; pa.bias[2] = blv; pa.C[2] = lvT; pa.mode[2] = 2; pa.presc[2] = 1.0f;
    hgemm<<<dim3(8, 32, 3), 256, gemm_smem>>>(pa, 1024, 2048);

    // tensor-core causal latent attention (double-buffered K/V)
    flash_tc<<<dim3(Sn / 128, Bn * Hn), 128, FSMEM>>>(q, lk, lvT, olat);

    // output projection
    HArgs po;
    po.A[0] = olat; po.BT[0] = wvoT; po.bias[0] = bout; po.C[0] = out; po.mode[0] = 0; po.presc[0] = 1.0f;
    hgemm<<<dim3(16, 32, 1), 256, gemm_smem>>>(po, 2048, 1024);
}